// round 9
// baseline (speedup 1.0000x reference)
#include <cuda_runtime.h>
#include <cstddef>

// KitNET_5257039970983 — R8: R7 (constant-bank folded weights, warp-local, no
// block barriers) + planar slice layout: STS.64 staging, LDS.128 xc reads,
// full-block specialization, precomputed staging maps.
// Output: head_out(B,10) then tails(B,10), fp32.

#define NTILES 10
#define CDIM   10
#define HDIM   7
#define FDIM   100
#define TPB    256
#define RPB    512
#define PSF    28                 // floats per pair slot (112B): h0[0..11] h1[12..23] pad
#define SLICE_F (32*PSF)          // 896 floats = 3584 B per warp

typedef unsigned long long u64;

struct FoldData {
    ulonglong2 MT[500];   // [t][co][ci pair]  (m,m)-packed
    ulonglong2 BT[50];    // [t][co pair]
    ulonglong2 MH[50];    // [j][i pair]
    ulonglong2 BH[5];
    int perm[100];
    int tbase[10];
    int pad[2];
};

__device__   FoldData gF;
__constant__ FoldData cF;

__device__ __forceinline__ u64 fma2(u64 a, u64 b, u64 c) {
    u64 d;
    asm("fma.rn.f32x2 %0, %1, %2, %3;" : "=l"(d) : "l"(a), "l"(b), "l"(c));
    return d;
}
__device__ __forceinline__ u64 pack2(float x, float y) {
    u64 d;
    asm("mov.b64 %0, {%1, %2};" : "=l"(d) : "f"(x), "f"(y));
    return d;
}
__device__ __forceinline__ void unpack2(u64 a, float& x, float& y) {
    asm("mov.b64 {%0, %1}, %2;" : "=f"(x), "=f"(y) : "l"(a));
}

// ================= setup kernel: fold weights into gF (1 block) =================
__global__ void kitnet_setup(const float* __restrict__ Wt,
                             const float* __restrict__ hbt,
                             const float* __restrict__ vbt,
                             const float* __restrict__ Wh,
                             const float* __restrict__ hbh,
                             const float* __restrict__ vbh,
                             const int*   __restrict__ clusters)
{
    __shared__ float sW[700], sHB[70], sVB[100], sWH[70], sHBH[7], sVBH[10];
    const int tid = threadIdx.x;
    for (int i = tid; i < 700; i += TPB) sW[i]  = Wt[i];
    for (int i = tid; i < 70;  i += TPB) sHB[i] = hbt[i];
    for (int i = tid; i < 100; i += TPB) sVB[i] = vbt[i];
    for (int i = tid; i < 70;  i += TPB) sWH[i] = Wh[i];
    if (tid < HDIM)   sHBH[tid] = hbh[tid];
    if (tid < NTILES) sVBH[tid] = vbh[tid];
    __syncthreads();

    float2* MT2 = (float2*)gF.MT;
    float2* BT2 = (float2*)gF.BT;
    float2* MH2 = (float2*)gF.MH;
    float2* BH2 = (float2*)gF.BH;

    for (int i = tid; i < NTILES * CDIM * CDIM; i += TPB) {
        int t  = i / 100;
        int r  = i - t * 100;
        int co = r / 10;
        int ci = r - co * 10;
        float m = (ci == co) ? -1.0f : 0.0f;
        #pragma unroll
        for (int h = 0; h < HDIM; ++h)
            m += sW[t * 70 + h * 10 + ci] * sW[t * 70 + h * 10 + co];
        MT2[i] = make_float2(m, m);
    }
    for (int i = tid; i < NTILES * CDIM; i += TPB) {
        int t = i / 10, c = i - t * 10;
        float b = sVB[i];
        #pragma unroll
        for (int h = 0; h < HDIM; ++h)
            b += sHB[t * HDIM + h] * sW[t * 70 + h * 10 + c];
        BT2[i] = make_float2(b, b);
    }
    for (int i = tid; i < CDIM * CDIM; i += TPB) {
        int j = i / 10, ii = i - j * 10;
        float m = 0.0f;
        #pragma unroll
        for (int h = 0; h < HDIM; ++h)
            m += sWH[h * 10 + ii] * sWH[h * 10 + j];
        MH2[i] = make_float2(m, m);
    }
    if (tid < NTILES) {
        float b = sVBH[tid];
        #pragma unroll
        for (int h = 0; h < HDIM; ++h)
            b += sHBH[h] * sWH[h * 10 + tid];
        BH2[tid] = make_float2(b, b);
    }
    for (int i = tid; i < FDIM; i += TPB) gF.perm[i] = clusters[i];
    if (tid < NTILES) {
        const int* pp = clusters + tid * 10;
        int b0 = pp[0];
        bool ok = ((b0 & 1) == 0);
        #pragma unroll
        for (int j = 1; j < 10; ++j) ok = ok && (pp[j] == b0 + j);
        gF.tbase[tid] = ok ? b0 : -1;
    }
}

// ================= main kernel =================

// err = xc @ M_t + b_t (constant bank); xc assembled from planar slice slot
__device__ __forceinline__ u64 compute_tile(const float* __restrict__ s0, int t)
{
    float4 a0 = *(const float4*)(s0);        // h0 f0..3
    float4 a1 = *(const float4*)(s0 + 4);    // h0 f4..7
    float4 a2 = *(const float4*)(s0 + 8);    // h0 f8,f9 (+2 junk)
    float4 b0 = *(const float4*)(s0 + 12);   // h1 f0..3
    float4 b1 = *(const float4*)(s0 + 16);   // h1 f4..7
    float4 b2 = *(const float4*)(s0 + 20);   // h1 f8,f9 (+2 junk)
    u64 xc[CDIM];
    xc[0] = pack2(a0.x, b0.x); xc[1] = pack2(a0.y, b0.y);
    xc[2] = pack2(a0.z, b0.z); xc[3] = pack2(a0.w, b0.w);
    xc[4] = pack2(a1.x, b1.x); xc[5] = pack2(a1.y, b1.y);
    xc[6] = pack2(a1.z, b1.z); xc[7] = pack2(a1.w, b1.w);
    xc[8] = pack2(a2.x, b2.x); xc[9] = pack2(a2.y, b2.y);

    const int mb  = t * 50;
    const int bb0 = t * 5;
    u64 sq = 0ull;
    #pragma unroll
    for (int cp = 0; cp < 5; ++cp) {
        ulonglong2 bb = cF.BT[bb0 + cp];
        u64 a0u = bb.x, a1u = bb.y;
        #pragma unroll
        for (int cc = 0; cc < 5; ++cc) {
            ulonglong2 w0 = cF.MT[mb + (2*cp)   * 5 + cc];
            ulonglong2 w1 = cF.MT[mb + (2*cp+1) * 5 + cc];
            a0u = fma2(xc[2*cc],   w0.x, a0u);
            a0u = fma2(xc[2*cc+1], w0.y, a0u);
            a1u = fma2(xc[2*cc],   w1.x, a1u);
            a1u = fma2(xc[2*cc+1], w1.y, a1u);
        }
        sq = fma2(a0u, a0u, sq);
        sq = fma2(a1u, a1u, sq);
    }
    return sq;
}

template<bool FULL>
__device__ __forceinline__ void run_rows(const float* __restrict__ x,
                                         float* __restrict__ out,
                                         float* __restrict__ slf,
                                         int rowbase, int B, int lane)
{
    const float* xg = x + (size_t)rowbase * FDIM;
    float2 rv[10];
    u64 tails[NTILES];

    // per-lane staging map (fast path): item i -> (p,h,k); packed goff|soff
    int emap[10];
    #pragma unroll
    for (int i = 0; i < 10; ++i) {
        int id = 32*i + lane;
        int p  = id / 10;
        int rem = id - 10*p;
        int h  = rem / 5;
        int k  = rem - 5*h;
        int goff = (p + h*256) * FDIM + 2*k;     // float offset in xg (add tb)
        int soff = p*PSF + h*12 + 2*k;           // float offset in slice
        emap[i] = goff | (soff << 17);
    }

    // ---- staging helpers inline (fast path uses emap; generic recomputes) ----
    auto load_t = [&](int t) {
        const int tb = cF.tbase[t];
        if (tb >= 0) {
            #pragma unroll
            for (int i = 0; i < 10; ++i) {
                int goff = emap[i] & 0x1FFFF;
                if (FULL) {
                    rv[i] = *(const float2*)(xg + goff + tb);
                } else {
                    // row = rowbase + goff/100 ; goff = row_off*100 + 2k (2k<10)
                    int row_off = goff / FDIM;
                    float2 v = make_float2(0.0f, 0.0f);
                    if (rowbase + row_off < B) v = *(const float2*)(xg + goff + tb);
                    rv[i] = v;
                }
            }
        } else {
            const int* pp = cF.perm + t * 10;
            #pragma unroll
            for (int i = 0; i < 10; ++i) {
                int id = 32*i + lane;
                int p  = id / 10;
                int rem = id - 10*p;
                int h  = rem / 5;
                int k  = rem - 5*h;
                int row_off = p + h*256;
                float v0 = 0.0f, v1 = 0.0f;
                if (FULL || rowbase + row_off < B) {
                    const float* rp = xg + row_off * FDIM;
                    v0 = rp[pp[2*k]];
                    v1 = rp[pp[2*k+1]];
                }
                rv[i] = make_float2(v0, v1);
            }
        }
    };
    auto store_t = [&]() {
        #pragma unroll
        for (int i = 0; i < 10; ++i) {
            int soff = emap[i] >> 17;
            *(float2*)(slf + soff) = rv[i];
        }
    };
    // NOTE: generic path loads perm columns pp[2k],pp[2k+1] which are exactly
    // slice floats (2k,2k+1) of row-half h — same soff mapping. Correct for both.

    // stage tile 0
    load_t(0);
    store_t();
    __syncwarp();

    const float* s0 = slf + lane * PSF;

    #pragma unroll 1
    for (int t = 0; t < NTILES; ++t) {
        if (t < NTILES - 1)
            load_t(t + 1);

        u64 sq = compute_tile(s0, t);
        float e0, e1;
        unpack2(sq, e0, e1);
        // 0.5*log(0.1*e) = 0.5*log(e) - 1.151292546...
        tails[t] = pack2(__fmaf_rn(0.5f, __logf(e0), -1.15129255f),
                         __fmaf_rn(0.5f, __logf(e1), -1.15129255f));

        __syncwarp();
        if (t < NTILES - 1)
            store_t();
        __syncwarp();
    }

    // ---- head: head_out = tails @ MH^T + b_h ----
    u64 ho[NTILES];
    #pragma unroll
    for (int jp = 0; jp < 5; ++jp) {
        ulonglong2 bb = cF.BH[jp];
        u64 a0 = bb.x, a1 = bb.y;
        #pragma unroll
        for (int tt = 0; tt < 5; ++tt) {
            ulonglong2 w0 = cF.MH[(2*jp)   * 5 + tt];
            ulonglong2 w1 = cF.MH[(2*jp+1) * 5 + tt];
            a0 = fma2(tails[2*tt],   w0.x, a0);
            a0 = fma2(tails[2*tt+1], w0.y, a0);
            a1 = fma2(tails[2*tt],   w1.x, a1);
            a1 = fma2(tails[2*tt+1], w1.y, a1);
        }
        ho[2*jp]   = a0;
        ho[2*jp+1] = a1;
    }

    // ---- warp-local output restage: round 0 = head, round 1 = tails ----
    const long long B10 = (long long)B * NTILES;
    #pragma unroll 1
    for (int r = 0; r < 2; ++r) {
        const u64* src = r ? tails : ho;
        #pragma unroll
        for (int n = 0; n < NTILES; ++n) {
            float a, b;
            unpack2(src[n], a, b);
            slf[lane * 10 + n]       = a;     // rows rowbase..+32
            slf[320 + lane * 10 + n] = b;     // rows rowbase+256..+32
        }
        __syncwarp();
        const long long bound = (long long)(r + 1) * B10;
        #pragma unroll
        for (int i = 0; i < 5; ++i) {
            int q  = lane + 32 * i;           // 0..159 float4 index
            int h  = (q >= 80) ? 1 : 0;
            int qq = q - 80 * h;
            long long off = (long long)r * B10
                          + (long long)(rowbase + h * 256) * 10 + 4 * qq;
            float4 v = *(const float4*)(slf + h * 320 + 4 * qq);
            if (FULL || off + 4 <= bound) {
                *(float4*)(out + off) = v;
            } else {
                const float* vf = (const float*)&v;
                #pragma unroll
                for (int kk = 0; kk < 4; ++kk)
                    if (off + kk < bound) out[off + kk] = vf[kk];
            }
        }
        __syncwarp();
    }
}

__global__ void __launch_bounds__(TPB, 3) kitnet_main(
    const float* __restrict__ x,
    float* __restrict__ out,
    int B)
{
    __shared__ float xs[8 * SLICE_F];          // 28672 B

    const int tid  = threadIdx.x;
    const int lane = tid & 31;
    const int wid  = tid >> 5;
    const int base = blockIdx.x * RPB;
    const int rowbase = base + wid * 32;
    float* slf = xs + wid * SLICE_F;

    if (base + RPB <= B)
        run_rows<true>(x, out, slf, rowbase, B, lane);
    else
        run_rows<false>(x, out, slf, rowbase, B, lane);
}

extern "C" void kernel_launch(void* const* d_in, const int* in_sizes, int n_in,
                              void* d_out, int out_size)
{
    const float* x   = (const float*)d_in[0];
    const float* Wt  = (const float*)d_in[1];
    const float* hbt = (const float*)d_in[2];
    const float* vbt = (const float*)d_in[3];
    const float* Wh  = (const float*)d_in[4];
    const float* hbh = (const float*)d_in[5];
    const float* vbh = (const float*)d_in[6];
    const int*   cls = (const int*)d_in[7];

    const int B = in_sizes[0] / FDIM;
    const int grid = (B + RPB - 1) / RPB;

    kitnet_setup<<<1, TPB>>>(Wt, hbt, vbt, Wh, hbh, vbh, cls);

    void* gfp = nullptr;
    cudaGetSymbolAddress(&gfp, gF);
    cudaMemcpyToSymbolAsync(cF, gfp, sizeof(FoldData), 0,
                            cudaMemcpyDeviceToDevice, 0);

    kitnet_main<<<grid, TPB>>>(x, (float*)d_out, B);
}